// round 1
// baseline (speedup 1.0000x reference)
#include <cuda_runtime.h>
#include <cstdint>

// Mosaic GEMM: out[256,8192] = x[256,8192] @ W + bias
//   W[k,n] = blocks[parts[k/64, n/64]][k%64][n%64]
// Round-1 SIMT fp32 kernel using packed fma.rn.f32x2 (sm_100+).

#define BM 64
#define BN 128
#define BK 64
#define AS_STRIDE 68   // 64 + 4 pad (transpose-write conflict relief), keeps 16B align
#define WS_STRIDE 128
#define KDIM 8192
#define NDIM 8192
#define NCHUNKS 128    // KDIM / BK

__device__ __forceinline__ unsigned long long pack2(float a) {
    unsigned long long r;
    asm("mov.b64 %0, {%1, %1};" : "=l"(r) : "f"(a));
    return r;
}

__device__ __forceinline__ void fma2(unsigned long long& acc,
                                     unsigned long long a,
                                     unsigned long long b) {
    asm("fma.rn.f32x2 %0, %1, %2, %0;" : "+l"(acc) : "l"(a), "l"(b));
}

__device__ __forceinline__ void unpack2(unsigned long long v, float& lo, float& hi) {
    asm("mov.b64 {%0, %1}, %2;" : "=f"(lo), "=f"(hi) : "l"(v));
}

__global__ void __launch_bounds__(256, 2)
mosaic_kernel(const float* __restrict__ x,
              const float* __restrict__ blocks,
              const float* __restrict__ bias,
              const int*   __restrict__ parts,
              float*       __restrict__ out)
{
    extern __shared__ float smem[];
    float* As = smem;                     // [BK][AS_STRIDE], layout As[k][m]
    float* Ws = smem + BK * AS_STRIDE;    // [BK][WS_STRIDE], layout Ws[k][n]

    const int tid = threadIdx.x;
    const int m0  = blockIdx.y * BM;
    const int n0  = blockIdx.x * BN;
    const int o0  = blockIdx.x * 2;       // two 64-wide mosaic columns per CTA

    const int ty = tid >> 5;              // 0..7  -> rows ty*8 .. +7
    const int tx = tid & 31;              // 0..31 -> cols tx*4 .. +3

    // A-tile load mapping: thread handles (row = tid/16 (+16*it), kgroup = tid%16)
    const int a_row = tid >> 4;           // 0..15
    const int a_cg  = tid & 15;           // 0..15 (k offset = a_cg*4)

    unsigned long long acc[8][2];
    #pragma unroll
    for (int r = 0; r < 8; ++r) { acc[r][0] = 0ull; acc[r][1] = 0ull; }

    for (int i = 0; i < NCHUNKS; ++i) {
        const int k0 = i * BK;
        const int p0 = parts[i * 128 + o0];
        const int p1 = parts[i * 128 + o0 + 1];

        __syncthreads();   // previous-iter smem reads done before overwrite

        // ---- load A tile [BM x BK], store transposed As[k][m] ----
        #pragma unroll
        for (int it = 0; it < 4; ++it) {
            const int row = a_row + it * 16;
            const float4 v = *reinterpret_cast<const float4*>(
                &x[(size_t)(m0 + row) * KDIM + k0 + a_cg * 4]);
            As[(a_cg * 4 + 0) * AS_STRIDE + row] = v.x;
            As[(a_cg * 4 + 1) * AS_STRIDE + row] = v.y;
            As[(a_cg * 4 + 2) * AS_STRIDE + row] = v.z;
            As[(a_cg * 4 + 3) * AS_STRIDE + row] = v.w;
        }

        // ---- load W tile: two 64x64 blocks -> Ws[k][0..63], Ws[k][64..127] ----
        const float* b0 = blocks + (size_t)p0 * 4096;
        const float* b1 = blocks + (size_t)p1 * 4096;
        #pragma unroll
        for (int it = 0; it < 4; ++it) {
            const int e4 = tid + it * 256;       // float4 index, 0..1023
            const int r  = e4 >> 4;              // row within block
            const int c4 = e4 & 15;              // float4 col within block
            const float4 v0 = *reinterpret_cast<const float4*>(&b0[e4 * 4]);
            const float4 v1 = *reinterpret_cast<const float4*>(&b1[e4 * 4]);
            *reinterpret_cast<float4*>(&Ws[r * WS_STRIDE + c4 * 4])      = v0;
            *reinterpret_cast<float4*>(&Ws[r * WS_STRIDE + 64 + c4 * 4]) = v1;
        }

        __syncthreads();

        // ---- compute: 64 k-steps, 8x4 register tile via f32x2 FMA ----
        #pragma unroll 8
        for (int kk = 0; kk < BK; ++kk) {
            const float4 a0 = *reinterpret_cast<const float4*>(&As[kk * AS_STRIDE + ty * 8]);
            const float4 a1 = *reinterpret_cast<const float4*>(&As[kk * AS_STRIDE + ty * 8 + 4]);
            const ulonglong2 w = *reinterpret_cast<const ulonglong2*>(&Ws[kk * WS_STRIDE + tx * 4]);

            const float ar[8] = {a0.x, a0.y, a0.z, a0.w, a1.x, a1.y, a1.z, a1.w};
            #pragma unroll
            for (int r = 0; r < 8; ++r) {
                const unsigned long long a2 = pack2(ar[r]);
                fma2(acc[r][0], a2, w.x);
                fma2(acc[r][1], a2, w.y);
            }
        }
    }

    // ---- epilogue: unpack, add bias, store ----
    const float4 bv = *reinterpret_cast<const float4*>(&bias[n0 + tx * 4]);
    #pragma unroll
    for (int r = 0; r < 8; ++r) {
        float c0, c1, c2, c3;
        unpack2(acc[r][0], c0, c1);
        unpack2(acc[r][1], c2, c3);
        float4 o;
        o.x = c0 + bv.x; o.y = c1 + bv.y; o.z = c2 + bv.z; o.w = c3 + bv.w;
        *reinterpret_cast<float4*>(
            &out[(size_t)(m0 + ty * 8 + r) * NDIM + n0 + tx * 4]) = o;
    }
}

extern "C" void kernel_launch(void* const* d_in, const int* in_sizes, int n_in,
                              void* d_out, int out_size) {
    const float* x      = (const float*)d_in[0];   // [256, 8192]
    const float* blocks = (const float*)d_in[1];   // [1024, 64, 64]
    const float* bias   = (const float*)d_in[2];   // [8192]
    const int*   parts  = (const int*)d_in[3];     // [128, 128]
    float* out = (float*)d_out;                    // [256, 8192]

    const size_t smem_bytes = (size_t)(BK * AS_STRIDE + BK * WS_STRIDE) * sizeof(float); // 50176
    cudaFuncSetAttribute(mosaic_kernel, cudaFuncAttributeMaxDynamicSharedMemorySize,
                         (int)smem_bytes);

    dim3 grid(NDIM / BN, 256 / BM);  // (64, 4)
    mosaic_kernel<<<grid, 256, smem_bytes>>>(x, blocks, bias, parts, out);
}

// round 4
// speedup vs baseline: 5.7566x; 5.7566x over previous
#include <cuda_runtime.h>
#include <cuda_fp16.h>
#include <cstdint>

// Mosaic GEMM via fp16 HMMA (mma.sync m16n8k16), single pass:
//   out[256,8192] = x @ W + bias,  W[k,n] = blocks[parts[k/64,n/64]][k%64][n%64]
// tcgen05 is unavailable (harness lowers via compute_103 without the 'a' feature),
// so we target the tensor pipe through base-ISA mma.sync + ldmatrix + cp.async.

#define KDIM 8192
#define NDIM 8192
#define BROWS 256
#define TM 128
#define TN 128
#define TK 64
#define NCHUNK 128          // KDIM / TK

#define A_STRIDE_B 144      // bytes per A smem row (64 halves + 8 pad)
#define B_STRIDE_B 272      // bytes per B smem row (128 halves + 8 pad)
#define A_BYTES (TM * A_STRIDE_B)          // 18432
#define B_BYTES (TK * B_STRIDE_B)          // 17408
#define STAGE_BYTES (A_BYTES + B_BYTES)    // 35840
#define SMEM_DYN (2 * STAGE_BYTES)         // 71680

static __device__ __half g_xh[BROWS * KDIM];        // fp16 x
static __device__ __half g_wh[1024 * 64 * 64];      // fp16 blocks (native [p][k][n])

// ---------------- helpers ----------------
__device__ __forceinline__ uint32_t smem_u32(const void* p) {
    uint32_t a;
    asm("{ .reg .u64 t; cvta.to.shared.u64 t, %1; cvt.u32.u64 %0, t; }" : "=r"(a) : "l"(p));
    return a;
}
__device__ __forceinline__ void cp16(uint32_t dst, const __half* src) {
    asm volatile("cp.async.cg.shared.global [%0], [%1], 16;"
                 :: "r"(dst), "l"(__cvta_generic_to_global(src)));
}
__device__ __forceinline__ void ldsm4(uint32_t* r, uint32_t addr) {
    asm volatile("ldmatrix.sync.aligned.m8n8.x4.shared.b16 {%0,%1,%2,%3}, [%4];"
        : "=r"(r[0]), "=r"(r[1]), "=r"(r[2]), "=r"(r[3]) : "r"(addr));
}
__device__ __forceinline__ void ldsm4t(uint32_t* r, uint32_t addr) {
    asm volatile("ldmatrix.sync.aligned.m8n8.x4.trans.shared.b16 {%0,%1,%2,%3}, [%4];"
        : "=r"(r[0]), "=r"(r[1]), "=r"(r[2]), "=r"(r[3]) : "r"(addr));
}
__device__ __forceinline__ void mma16816(float* c, const uint32_t* a,
                                         uint32_t b0, uint32_t b1) {
    asm volatile(
        "mma.sync.aligned.m16n8k16.row.col.f32.f16.f16.f32 "
        "{%0,%1,%2,%3}, {%4,%5,%6,%7}, {%8,%9}, {%0,%1,%2,%3};"
        : "+f"(c[0]), "+f"(c[1]), "+f"(c[2]), "+f"(c[3])
        : "r"(a[0]), "r"(a[1]), "r"(a[2]), "r"(a[3]), "r"(b0), "r"(b1));
}

// ---------------- conversion kernels ----------------
__global__ void convert_x_kernel(const float* __restrict__ x) {
    const int i = (blockIdx.x * blockDim.x + threadIdx.x) * 4;
    const float4 v = *reinterpret_cast<const float4*>(x + i);
    *reinterpret_cast<__half2*>(g_xh + i)     = __floats2half2_rn(v.x, v.y);
    *reinterpret_cast<__half2*>(g_xh + i + 2) = __floats2half2_rn(v.z, v.w);
}
__global__ void convert_b_kernel(const float* __restrict__ blocks) {
    const size_t i = ((size_t)blockIdx.x * blockDim.x + threadIdx.x) * 4;
    const float4 v = *reinterpret_cast<const float4*>(blocks + i);
    *reinterpret_cast<__half2*>(g_wh + i)     = __floats2half2_rn(v.x, v.y);
    *reinterpret_cast<__half2*>(g_wh + i + 2) = __floats2half2_rn(v.z, v.w);
}

// ---------------- main kernel ----------------
__global__ void __launch_bounds__(256, 1)
mosaic_hmma_kernel(const int* __restrict__ parts,
                   const float* __restrict__ bias,
                   float* __restrict__ out)
{
    extern __shared__ __align__(128) char smem[];
    const uint32_t sb = smem_u32(smem);
    const int tid  = threadIdx.x;
    const int wid  = tid >> 5;
    const int lane = tid & 31;
    const int m0 = blockIdx.y * TM;
    const int n0 = blockIdx.x * TN;
    const int o0 = blockIdx.x * 2;

    const int wm = (wid & 3) * 32;     // warp m offset within CTA tile
    const int wn = (wid >> 2) * 64;    // warp n offset within CTA tile
    const int lrow = lane & 15;        // ldmatrix row (both A and B-trans)
    const int lcol = (lane >> 4) * 8;  // ldmatrix col-group (halves)

    float acc[2][8][4];
    #pragma unroll
    for (int a = 0; a < 2; ++a)
        #pragma unroll
        for (int b = 0; b < 8; ++b)
            #pragma unroll
            for (int c = 0; c < 4; ++c) acc[a][b][c] = 0.f;

    // -------- async tile loader --------
    auto issue = [&](int i) {
        const int s = i & 1;
        const uint32_t abase = sb + s * STAGE_BYTES;
        const uint32_t bbase = abase + A_BYTES;
        const int p0 = parts[i * 128 + o0];
        const int p1 = parts[i * 128 + o0 + 1];
        const size_t k0 = (size_t)i * TK;
        // A: 128 rows x 64 halves (8 x 16B per row) = 1024 chunks
        #pragma unroll
        for (int it = 0; it < 4; ++it) {
            const int e = tid + it * 256;
            const int r = e >> 3, c = e & 7;
            cp16(abase + r * A_STRIDE_B + c * 16,
                 g_xh + (size_t)(m0 + r) * KDIM + k0 + c * 8);
        }
        // B: 64 rows x 128 halves (16 x 16B per row) = 1024 chunks
        #pragma unroll
        for (int it = 0; it < 4; ++it) {
            const int e = tid + it * 256;
            const int r = e >> 4, c = e & 15;
            const int p = (c < 8) ? p0 : p1;
            cp16(bbase + r * B_STRIDE_B + c * 16,
                 g_wh + ((size_t)p << 12) + r * 64 + (c & 7) * 8);
        }
        asm volatile("cp.async.commit_group;" ::: "memory");
    };

    issue(0);

    for (int i = 0; i < NCHUNK; ++i) {
        if (i + 1 < NCHUNK) {
            issue(i + 1);
            asm volatile("cp.async.wait_group 1;" ::: "memory");
        } else {
            asm volatile("cp.async.wait_group 0;" ::: "memory");
        }
        __syncthreads();

        const uint32_t abase = sb + (i & 1) * STAGE_BYTES;
        const uint32_t bbase = abase + A_BYTES;
        const uint32_t a_ad = abase + (wm + lrow) * A_STRIDE_B + lcol * 2;
        const uint32_t b_ad = bbase + lrow * B_STRIDE_B + (wn + lcol) * 2;

        #pragma unroll
        for (int kk = 0; kk < 4; ++kk) {      // four k16 steps
            uint32_t af[2][4];
            ldsm4(af[0], a_ad + kk * 32);
            ldsm4(af[1], a_ad + 16 * A_STRIDE_B + kk * 32);
            uint32_t bf[4][4];
            #pragma unroll
            for (int nt = 0; nt < 4; ++nt)
                ldsm4t(bf[nt], b_ad + kk * 16 * B_STRIDE_B + nt * 32);
            #pragma unroll
            for (int mt = 0; mt < 2; ++mt)
                #pragma unroll
                for (int nt = 0; nt < 4; ++nt) {
                    mma16816(acc[mt][nt * 2 + 0], af[mt], bf[nt][0], bf[nt][1]);
                    mma16816(acc[mt][nt * 2 + 1], af[mt], bf[nt][2], bf[nt][3]);
                }
        }
        __syncthreads();
    }

    // -------- epilogue: bias + store --------
    const int qr = lane >> 2;
    const int qc = (lane & 3) * 2;
    #pragma unroll
    for (int mt = 0; mt < 2; ++mt) {
        const size_t r0 = (size_t)(m0 + wm + mt * 16 + qr);
        #pragma unroll
        for (int nj = 0; nj < 8; ++nj) {
            const int col = n0 + wn + nj * 8 + qc;
            const float2 bv = *reinterpret_cast<const float2*>(bias + col);
            float2 lo, hi;
            lo.x = acc[mt][nj][0] + bv.x;  lo.y = acc[mt][nj][1] + bv.y;
            hi.x = acc[mt][nj][2] + bv.x;  hi.y = acc[mt][nj][3] + bv.y;
            *reinterpret_cast<float2*>(out + r0 * NDIM + col)       = lo;
            *reinterpret_cast<float2*>(out + (r0 + 8) * NDIM + col) = hi;
        }
    }
}

// ---------------- launch ----------------
extern "C" void kernel_launch(void* const* d_in, const int* in_sizes, int n_in,
                              void* d_out, int out_size) {
    const float* x      = (const float*)d_in[0];   // [256, 8192]
    const float* blocks = (const float*)d_in[1];   // [1024, 64, 64]
    const float* bias   = (const float*)d_in[2];   // [8192]
    const int*   parts  = (const int*)d_in[3];     // [128, 128]
    float* out = (float*)d_out;                    // [256, 8192]

    convert_x_kernel<<<(BROWS * KDIM) / (256 * 4), 256>>>(x);
    convert_b_kernel<<<(1024 * 64 * 64) / (256 * 4), 256>>>(blocks);

    cudaFuncSetAttribute(mosaic_hmma_kernel,
                         cudaFuncAttributeMaxDynamicSharedMemorySize, SMEM_DYN);
    dim3 grid(NDIM / TN, BROWS / TM);   // (64, 2)
    mosaic_hmma_kernel<<<grid, 256, SMEM_DYN>>>(parts, bias, out);
}

// round 5
// speedup vs baseline: 5.9088x; 1.0264x over previous
#include <cuda_runtime.h>
#include <cuda_fp16.h>
#include <cstdint>

// Mosaic GEMM via fp16 HMMA (mma.sync m16n8k16), single pass, 4-stage cp.async:
//   out[256,8192] = x @ W + bias,  W[k,n] = blocks[parts[k/64,n/64]][k%64][n%64]

#define KDIM 8192
#define NDIM 8192
#define BROWS 256
#define TM 128
#define TN 128
#define TK 64
#define NCHUNK 128          // KDIM / TK

#define A_STRIDE_B 144      // bytes per A smem row (64 halves + 8 pad)
#define B_STRIDE_B 272      // bytes per B smem row (128 halves + 8 pad)
#define A_BYTES (TM * A_STRIDE_B)          // 18432
#define B_BYTES (TK * B_STRIDE_B)          // 17408
#define STAGE_BYTES (A_BYTES + B_BYTES)    // 35840
#define NSTAGE 4
#define SMEM_DYN (NSTAGE * STAGE_BYTES)    // 143360

static __device__ __half g_xh[BROWS * KDIM];        // fp16 x
static __device__ __half g_wh[1024 * 64 * 64];      // fp16 blocks (native [p][k][n])

// ---------------- helpers ----------------
__device__ __forceinline__ uint32_t smem_u32(const void* p) {
    uint32_t a;
    asm("{ .reg .u64 t; cvta.to.shared.u64 t, %1; cvt.u32.u64 %0, t; }" : "=r"(a) : "l"(p));
    return a;
}
__device__ __forceinline__ void cp16(uint32_t dst, const __half* src) {
    asm volatile("cp.async.cg.shared.global [%0], [%1], 16;"
                 :: "r"(dst), "l"(__cvta_generic_to_global(src)));
}
__device__ __forceinline__ void ldsm4(uint32_t* r, uint32_t addr) {
    asm volatile("ldmatrix.sync.aligned.m8n8.x4.shared.b16 {%0,%1,%2,%3}, [%4];"
        : "=r"(r[0]), "=r"(r[1]), "=r"(r[2]), "=r"(r[3]) : "r"(addr));
}
__device__ __forceinline__ void ldsm4t(uint32_t* r, uint32_t addr) {
    asm volatile("ldmatrix.sync.aligned.m8n8.x4.trans.shared.b16 {%0,%1,%2,%3}, [%4];"
        : "=r"(r[0]), "=r"(r[1]), "=r"(r[2]), "=r"(r[3]) : "r"(addr));
}
__device__ __forceinline__ void mma16816(float* c, const uint32_t* a,
                                         uint32_t b0, uint32_t b1) {
    asm volatile(
        "mma.sync.aligned.m16n8k16.row.col.f32.f16.f16.f32 "
        "{%0,%1,%2,%3}, {%4,%5,%6,%7}, {%8,%9}, {%0,%1,%2,%3};"
        : "+f"(c[0]), "+f"(c[1]), "+f"(c[2]), "+f"(c[3])
        : "r"(a[0]), "r"(a[1]), "r"(a[2]), "r"(a[3]), "r"(b0), "r"(b1));
}

// ---------------- fused conversion kernel ----------------
// blocks [0,2048): x (256*8192 fp32); blocks [2048,6144): block bank (1024*4096 fp32)
__global__ void convert_all_kernel(const float* __restrict__ x,
                                   const float* __restrict__ blocks) {
    const int b = blockIdx.x;
    if (b < 2048) {
        const int i = (b * 256 + threadIdx.x) * 4;
        const float4 v = *reinterpret_cast<const float4*>(x + i);
        *reinterpret_cast<__half2*>(g_xh + i)     = __floats2half2_rn(v.x, v.y);
        *reinterpret_cast<__half2*>(g_xh + i + 2) = __floats2half2_rn(v.z, v.w);
    } else {
        const size_t i = ((size_t)(b - 2048) * 256 + threadIdx.x) * 4;
        const float4 v = *reinterpret_cast<const float4*>(blocks + i);
        *reinterpret_cast<__half2*>(g_wh + i)     = __floats2half2_rn(v.x, v.y);
        *reinterpret_cast<__half2*>(g_wh + i + 2) = __floats2half2_rn(v.z, v.w);
    }
}

// ---------------- main kernel ----------------
__global__ void __launch_bounds__(256, 1)
mosaic_hmma_kernel(const int* __restrict__ parts,
                   const float* __restrict__ bias,
                   float* __restrict__ out)
{
    extern __shared__ __align__(128) char smem[];
    const uint32_t sb = smem_u32(smem);
    const int tid  = threadIdx.x;
    const int wid  = tid >> 5;
    const int lane = tid & 31;
    const int m0 = blockIdx.y * TM;
    const int n0 = blockIdx.x * TN;
    const int o0 = blockIdx.x * 2;

    const int wm = (wid & 3) * 32;     // warp m offset
    const int wn = (wid >> 2) * 64;    // warp n offset
    const int lrow = lane & 15;
    const int lcol = (lane >> 4) * 8;

    float acc[2][8][4];
    #pragma unroll
    for (int a = 0; a < 2; ++a)
        #pragma unroll
        for (int b = 0; b < 8; ++b)
            #pragma unroll
            for (int c = 0; c < 4; ++c) acc[a][b][c] = 0.f;

    // per-thread cp.async source/dest mapping (constant across chunks)
    const int ar = tid >> 3,  ac = tid & 7;    // A: rows tid/8 (+32*it), col-16B tid%8
    const int br = tid >> 4,  bc = tid & 15;   // B: rows tid/16 (+16*it), col-16B tid%16

    auto issue = [&](int i) {
        if (i < NCHUNK) {
            const int s = i & (NSTAGE - 1);
            const uint32_t abase = sb + s * STAGE_BYTES;
            const uint32_t bbase = abase + A_BYTES;
            const int p0 = parts[i * 128 + o0];
            const int p1 = parts[i * 128 + o0 + 1];
            const size_t k0 = (size_t)i * TK;
            const __half* asrc = g_xh + (size_t)(m0 + ar) * KDIM + k0 + ac * 8;
            #pragma unroll
            for (int it = 0; it < 4; ++it)
                cp16(abase + (ar + it * 32) * A_STRIDE_B + ac * 16,
                     asrc + (size_t)it * 32 * KDIM);
            const __half* bsrc = g_wh + ((size_t)((bc < 8) ? p0 : p1) << 12)
                               + br * 64 + (bc & 7) * 8;
            #pragma unroll
            for (int it = 0; it < 4; ++it)
                cp16(bbase + (br + it * 16) * B_STRIDE_B + bc * 16,
                     bsrc + it * 16 * 64);
        }
        asm volatile("cp.async.commit_group;" ::: "memory");
    };

    issue(0); issue(1); issue(2);

    for (int i = 0; i < NCHUNK; ++i) {
        asm volatile("cp.async.wait_group 2;" ::: "memory");
        __syncthreads();
        issue(i + 3);

        const uint32_t abase = sb + (i & (NSTAGE - 1)) * STAGE_BYTES;
        const uint32_t bbase = abase + A_BYTES;
        const uint32_t a_ad = abase + (wm + lrow) * A_STRIDE_B + lcol * 2;
        const uint32_t b_ad = bbase + lrow * B_STRIDE_B + (wn + lcol) * 2;

        #pragma unroll
        for (int kk = 0; kk < 4; ++kk) {
            uint32_t af[2][4];
            ldsm4(af[0], a_ad + kk * 32);
            ldsm4(af[1], a_ad + 16 * A_STRIDE_B + kk * 32);
            uint32_t bf[4][4];
            #pragma unroll
            for (int nt = 0; nt < 4; ++nt)
                ldsm4t(bf[nt], b_ad + kk * 16 * B_STRIDE_B + nt * 32);
            #pragma unroll
            for (int mt = 0; mt < 2; ++mt)
                #pragma unroll
                for (int nt = 0; nt < 4; ++nt) {
                    mma16816(acc[mt][nt * 2 + 0], af[mt], bf[nt][0], bf[nt][1]);
                    mma16816(acc[mt][nt * 2 + 1], af[mt], bf[nt][2], bf[nt][3]);
                }
        }
    }

    // -------- epilogue: bias + store --------
    const int qr = lane >> 2;
    const int qc = (lane & 3) * 2;
    #pragma unroll
    for (int mt = 0; mt < 2; ++mt) {
        const size_t r0 = (size_t)(m0 + wm + mt * 16 + qr);
        #pragma unroll
        for (int nj = 0; nj < 8; ++nj) {
            const int col = n0 + wn + nj * 8 + qc;
            const float2 bv = *reinterpret_cast<const float2*>(bias + col);
            float2 lo, hi;
            lo.x = acc[mt][nj][0] + bv.x;  lo.y = acc[mt][nj][1] + bv.y;
            hi.x = acc[mt][nj][2] + bv.x;  hi.y = acc[mt][nj][3] + bv.y;
            *reinterpret_cast<float2*>(out + r0 * NDIM + col)       = lo;
            *reinterpret_cast<float2*>(out + (r0 + 8) * NDIM + col) = hi;
        }
    }
}

// ---------------- launch ----------------
extern "C" void kernel_launch(void* const* d_in, const int* in_sizes, int n_in,
                              void* d_out, int out_size) {
    const float* x      = (const float*)d_in[0];   // [256, 8192]
    const float* blocks = (const float*)d_in[1];   // [1024, 64, 64]
    const float* bias   = (const float*)d_in[2];   // [8192]
    const int*   parts  = (const int*)d_in[3];     // [128, 128]
    float* out = (float*)d_out;                    // [256, 8192]

    convert_all_kernel<<<6144, 256>>>(x, blocks);

    cudaFuncSetAttribute(mosaic_hmma_kernel,
                         cudaFuncAttributeMaxDynamicSharedMemorySize, SMEM_DYN);
    dim3 grid(NDIM / TN, BROWS / TM);   // (64, 2)
    mosaic_hmma_kernel<<<grid, 256, SMEM_DYN>>>(parts, bias, out);
}